// round 9
// baseline (speedup 1.0000x reference)
#include <cuda_runtime.h>
#include <cstdint>

#define BB 8
#define DD 8
#define KK 5
#define PP (512*1024)

// ---- scratch (device globals; zero-initialized at module load; finalize
// resets them at the end of every run so graph replays start clean) ----
__device__ float g_sums[BB][KK][DD];   // per-batch per-instance channel sums
__device__ int   g_cnt[BB][KK + 1];    // per-batch per-slot pixel counts
__device__ float g_var[BB][KK + 1];    // per-batch per-slot variance sums

// ---------------------------------------------------------------------------
// Pass 1: channel-split with REGISTER accumulators. Warp w of each block owns
// channel plane w; all 8 warps sweep the same pixel window (mask int4 loads
// dedupe in L1). Each thread keeps acc[5] registers; per pixel 5 predicated
// adds. Processes HALF the batch (4 images) per launch so that the half's
// 72 MB working set stays L2-resident for the matching pass2 launch.
#define T1 256
#define GX1 512
#define ITER1 8
// coverage: GX1 * 32 lanes * 4 px * ITER1 = 524288 = PP exactly

__global__ void __launch_bounds__(T1) pass1_kernel(const float* __restrict__ emb,
                                                   const int* __restrict__ mask,
                                                   int b0) {
    __shared__ float red[DD][KK];
    const int t = threadIdx.x;
    const int b = b0 + blockIdx.y;
    const int w = t >> 5, lane = t & 31;   // w = channel index

    float acc[KK];
#pragma unroll
    for (int k = 0; k < KK; k++) acc[k] = 0.f;

    unsigned long long cnt64 = 0ull;
    const float* ep = emb + (size_t)b * DD * PP + (size_t)w * PP;
    const int*   mb = mask + (size_t)b * PP;
    int p = (blockIdx.x * 32 + lane) * 4;
    const int stride = GX1 * 32 * 4;

#pragma unroll
    for (int it = 0; it < ITER1; it++, p += stride) {
        const int4 lab4 = *reinterpret_cast<const int4*>(mb + p);
        const float4 v  = *reinterpret_cast<const float4*>(ep + p);
        const int labs[4] = {lab4.x, lab4.y, lab4.z, lab4.w};
        const float es[4] = {v.x, v.y, v.z, v.w};
#pragma unroll
        for (int i = 0; i < 4; i++) {
            const int lab = labs[i];
            if (w == 0) cnt64 += 1ull << (lab * 8);
#pragma unroll
            for (int k = 0; k < KK; k++)
                if (lab == k + 1) acc[k] += es[i];
        }
    }

    // per-warp reduction: 5 instance sums for channel w
#pragma unroll
    for (int off = 16; off > 0; off >>= 1) {
#pragma unroll
        for (int k = 0; k < KK; k++)
            acc[k] += __shfl_down_sync(0xffffffffu, acc[k], off);
    }
    if (lane == 0) {
#pragma unroll
        for (int k = 0; k < KK; k++) red[w][k] = acc[k];
    }
    __syncthreads();
    if (t < KK * DD) {
        const int k = t >> 3, d = t & 7;        // g_sums layout [k][d]
        atomicAdd(&g_sums[b][k][d], red[d][k]);
    }

    // counts from warp 0 only (each label count <= 32 fits a byte)
    if (w == 0) {
#pragma unroll
        for (int k = 1; k <= KK; k++) {
            unsigned c = (unsigned)((cnt64 >> (8 * k)) & 0xffull);
            c = __reduce_add_sync(0xffffffffu, c);
            if (lane == 0) atomicAdd(&g_cnt[b][k], (int)c);
        }
    }
}

// ---------------------------------------------------------------------------
// Pass 2: per-pixel hinge-variance term (smem per-thread slots for the 6
// label accumulators), centers computed inline in the prologue. Runs on the
// half-batch that pass1 just pulled through L2.
#define T2 256
#define VSLOT 9
#define GX2 128

__device__ __forceinline__ float fsqrt_approx(float x) {
    float r;
    asm("sqrt.approx.f32 %0, %1;" : "=f"(r) : "f"(x));
    return r;
}

__global__ void __launch_bounds__(T2) pass2_kernel(const float* __restrict__ emb,
                                                   const int* __restrict__ mask,
                                                   int b0) {
    __shared__ float4 cs4[(KK + 1) * 2];   // centers table, float4-aligned
    __shared__ float vacc[T2 * VSLOT];
    const int t = threadIdx.x;
    const int b = b0 + blockIdx.y;

    if (t < (KK + 1) * DD) {
        const int slot = t / DD, d = t % DD;
        float v = 0.f;
        if (slot >= 1)
            v = g_sums[b][slot - 1][d] / fmaxf((float)g_cnt[b][slot], 1.f);
        reinterpret_cast<float*>(cs4)[t] = v;
    }
#pragma unroll
    for (int j = 0; j < VSLOT; j++) vacc[t * VSLOT + j] = 0.f;
    __syncthreads();

    const float* eb = emb + (size_t)b * DD * PP;
    const int*   mb = mask + (size_t)b * PP;
    const int stride = GX2 * T2 * 4;

    for (int p0 = (blockIdx.x * T2 + t) * 4; p0 < PP; p0 += stride) {
        const int4 lab4 = *reinterpret_cast<const int4*>(mb + p0);
        float ev[4][DD];
#pragma unroll
        for (int d = 0; d < DD; d++) {
            float4 v = *reinterpret_cast<const float4*>(eb + (size_t)d * PP + p0);
            ev[0][d] = v.x; ev[1][d] = v.y; ev[2][d] = v.z; ev[3][d] = v.w;
        }
        int labs[4] = {lab4.x, lab4.y, lab4.z, lab4.w};
#pragma unroll
        for (int i = 0; i < 4; i++) {
            const int lab = labs[i];
            const float4 clo = cs4[lab * 2];
            const float4 chi = cs4[lab * 2 + 1];
            float d0 = ev[i][0] - clo.x;
            float s  = d0 * d0;
            float d1 = ev[i][1] - clo.y; s = fmaf(d1, d1, s);
            float d2 = ev[i][2] - clo.z; s = fmaf(d2, d2, s);
            float d3 = ev[i][3] - clo.w; s = fmaf(d3, d3, s);
            float d4 = ev[i][4] - chi.x; s = fmaf(d4, d4, s);
            float d5 = ev[i][5] - chi.y; s = fmaf(d5, d5, s);
            float d6 = ev[i][6] - chi.z; s = fmaf(d6, d6, s);
            float d7 = ev[i][7] - chi.w; s = fmaf(d7, d7, s);
            // max(sqrt(s)-0.5,0)^2 == s - sqrt(s) + 0.25 when s > 0.25 else 0
            float val = (s - fsqrt_approx(s)) + 0.25f;
            val = (s > 0.25f) ? val : 0.f;
            vacc[t * VSLOT + lab] += val;
        }
    }

    __syncthreads();
    for (int off = T2 / 2; off > 0; off >>= 1) {
        if (t < off) {
            float* a = vacc + t * VSLOT;
            float* c = vacc + (t + off) * VSLOT;
#pragma unroll
            for (int j = 0; j < 6; j++) a[j] += c[j];
        }
        __syncthreads();
    }
    if (t >= 1 && t <= KK) atomicAdd(&g_var[b][t], vacc[t]);
}

// ---------------------------------------------------------------------------
// Finalize: cooperative smem preload of all scratch, per-b epilogue, output
// write, and scratch reset for the next graph replay.
#define TF 320

__global__ void __launch_bounds__(TF) finalize_kernel(float* __restrict__ out) {
    __shared__ float sh_sums[BB][KK][DD];
    __shared__ float sh_cnt[BB][KK + 1];
    __shared__ float sh_varr[BB][KK + 1];
    __shared__ float s_var[BB], s_dist[BB], s_reg[BB], s_has[BB];
    const int t = threadIdx.x;

    if (t < BB * KK * DD) (&sh_sums[0][0][0])[t] = (&g_sums[0][0][0])[t];
    if (t < BB * (KK + 1)) {
        (&sh_cnt[0][0])[t]  = (float)(&g_cnt[0][0])[t];
        (&sh_varr[0][0])[t] = (&g_var[0][0])[t];
    }
    __syncthreads();

    if (t < BB) {
        const int b = t;
        float cnt[KK], present[KK], N = 0.f;
        float ctr[KK][DD];
#pragma unroll
        for (int k = 0; k < KK; k++) {
            cnt[k] = sh_cnt[b][k + 1];
            present[k] = cnt[k] > 0.f ? 1.f : 0.f;
            N += present[k];
            const float inv = 1.f / fmaxf(cnt[k], 1.f);
#pragma unroll
            for (int d = 0; d < DD; d++) ctr[k][d] = sh_sums[b][k][d] * inv;
        }
        float lv = 0.f;
#pragma unroll
        for (int k = 0; k < KK; k++)
            lv += present[k] * (sh_varr[b][k + 1] / fmaxf(cnt[k], 1.f));
        lv /= fmaxf(N, 1.f);

        float ld = 0.f;
        for (int i = 0; i < KK; i++) {
            for (int j = i + 1; j < KK; j++) {
                if (present[i] > 0.f && present[j] > 0.f) {
                    float dsq = 0.f;
#pragma unroll
                    for (int d = 0; d < DD; d++) {
                        float df = ctr[i][d] - ctr[j][d];
                        dsq = fmaf(df, df, dsq);
                    }
                    float dist = sqrtf(dsq);
                    float term = fmaxf(6.0f - dist, 0.f);  // 2*DELTA_D = 6
                    ld += term * term;
                }
            }
        }
        float npairs = N * (N - 1.f) * 0.5f;
        ld /= (N > 1.f) ? npairs : 1.f;

        float lr = 0.f;
#pragma unroll
        for (int k = 0; k < KK; k++) {
            if (present[k] > 0.f) {
                float nsq = 0.f;
#pragma unroll
                for (int d = 0; d < DD; d++) {
                    float c = ctr[k][d];
                    nsq = fmaf(c, c, nsq);
                }
                lr += sqrtf(nsq);
            }
        }
        lr /= fmaxf(N, 1.f);
        s_var[b] = lv; s_dist[b] = ld; s_reg[b] = lr;
        s_has[b] = (N > 0.f) ? 1.f : 0.f;
    }
    __syncthreads();
    if (t == 0) {
        float hv = 0.f, hd = 0.f, hr = 0.f, hh = 0.f;
#pragma unroll
        for (int b = 0; b < BB; b++) {
            hh += s_has[b];
            hv += s_var[b] * s_has[b];
            hd += s_dist[b] * s_has[b];
            hr += s_reg[b] * s_has[b];
        }
        const float den = fmaxf(hh, 1.f);
        const float var = hv / den, dist = hd / den, reg = hr / den;
        out[0] = var + dist + 0.001f * reg;  // ALPHA=BETA=1, GAMMA=0.001
        out[1] = var;
        out[2] = dist;
        out[3] = reg;
    }

    // reset scratch for the next graph replay
    if (t < BB * KK * DD) (&g_sums[0][0][0])[t] = 0.f;
    if (t < BB * (KK + 1)) {
        (&g_cnt[0][0])[t] = 0;
        (&g_var[0][0])[t] = 0.f;
    }
}

// ---------------------------------------------------------------------------
extern "C" void kernel_launch(void* const* d_in, const int* in_sizes, int n_in,
                              void* d_out, int out_size) {
    const float* emb  = (const float*)d_in[0];
    const int*   mask = (const int*)d_in[1];
    float*       out  = (float*)d_out;

    const int HB = BB / 2;  // 4 images per half: 72 MB, L2-resident
    for (int h = 0; h < 2; h++) {
        const int b0 = h * HB;
        dim3 g1(GX1, HB);
        pass1_kernel<<<g1, T1>>>(emb, mask, b0);
        dim3 g2(GX2, HB);
        pass2_kernel<<<g2, T2>>>(emb, mask, b0);
    }
    finalize_kernel<<<1, TF>>>(out);
}

// round 10
// speedup vs baseline: 1.5645x; 1.5645x over previous
#include <cuda_runtime.h>
#include <cstdint>

#define BB 8
#define DD 8
#define KK 5
#define PP (512*1024)

// ---- scratch (device globals; zero-initialized at module load; finalize
// resets them at the end of every run so graph replays start clean) ----
__device__ float g_sums[BB][KK][DD];   // per-batch per-instance channel sums
__device__ int   g_cnt[BB][KK + 1];    // per-batch per-slot pixel counts
__device__ float g_var[BB][KK + 1];    // per-batch per-slot variance sums

// ---------------------------------------------------------------------------
// Pass 1: channel-split, 2 channels per thread. Warp w (of 4) owns channel
// planes w and w+4; all 4 warps sweep the same pixel window (mask int4 loads
// dedupe in L1, now only 4x replicated). Per pixel: 5 ISETP shared across the
// 2 channels + 10 predicated FADDs. acc = 10 registers.
#define T1 128
#define GX1 512
#define ITER1 8
// coverage: GX1 * 32 lanes * 4 px * ITER1 = 524288 = PP exactly

__global__ void __launch_bounds__(T1) pass1_kernel(const float* __restrict__ emb,
                                                   const int* __restrict__ mask) {
    __shared__ float red[DD][KK];
    const int t = threadIdx.x;
    const int b = blockIdx.y;
    const int w = t >> 5, lane = t & 31;   // w = low channel index (0..3)

    float acc0[KK], acc1[KK];
#pragma unroll
    for (int k = 0; k < KK; k++) { acc0[k] = 0.f; acc1[k] = 0.f; }

    unsigned long long cnt64 = 0ull;
    const float* ep0 = emb + (size_t)b * DD * PP + (size_t)w * PP;
    const float* ep1 = ep0 + (size_t)4 * PP;
    const int*   mb  = mask + (size_t)b * PP;
    int p = (blockIdx.x * 32 + lane) * 4;
    const int stride = GX1 * 32 * 4;

#pragma unroll
    for (int it = 0; it < ITER1; it++, p += stride) {
        const int4 lab4 = *reinterpret_cast<const int4*>(mb + p);
        const float4 v0 = *reinterpret_cast<const float4*>(ep0 + p);
        const float4 v1 = *reinterpret_cast<const float4*>(ep1 + p);
        const int labs[4] = {lab4.x, lab4.y, lab4.z, lab4.w};
        const float e0[4] = {v0.x, v0.y, v0.z, v0.w};
        const float e1[4] = {v1.x, v1.y, v1.z, v1.w};
#pragma unroll
        for (int i = 0; i < 4; i++) {
            const int lab = labs[i];
            if (w == 0) cnt64 += 1ull << (lab * 8);
#pragma unroll
            for (int k = 0; k < KK; k++) {
                if (lab == k + 1) {
                    acc0[k] += e0[i];
                    acc1[k] += e1[i];
                }
            }
        }
    }

    // per-warp reduction: 5 instance sums for each of the 2 channels
#pragma unroll
    for (int off = 16; off > 0; off >>= 1) {
#pragma unroll
        for (int k = 0; k < KK; k++) {
            acc0[k] += __shfl_down_sync(0xffffffffu, acc0[k], off);
            acc1[k] += __shfl_down_sync(0xffffffffu, acc1[k], off);
        }
    }
    if (lane == 0) {
#pragma unroll
        for (int k = 0; k < KK; k++) {
            red[w][k]     = acc0[k];
            red[w + 4][k] = acc1[k];
        }
    }
    __syncthreads();
    if (t < KK * DD) {
        const int k = t >> 3, d = t & 7;        // g_sums layout [k][d]
        atomicAdd(&g_sums[b][k][d], red[d][k]);
    }

    // counts from warp 0 only (each label count <= 32 fits a byte)
    if (w == 0) {
#pragma unroll
        for (int k = 1; k <= KK; k++) {
            unsigned c = (unsigned)((cnt64 >> (8 * k)) & 0xffull);
            c = __reduce_add_sync(0xffffffffu, c);
            if (lane == 0) atomicAdd(&g_cnt[b][k], (int)c);
        }
    }
}

// ---------------------------------------------------------------------------
// Pass 2: per-pixel hinge-variance term (smem per-thread slots for the 6
// label accumulators), centers computed inline in the prologue.
#define T2 256
#define VSLOT 9
#define GX2 128

__device__ __forceinline__ float fsqrt_approx(float x) {
    float r;
    asm("sqrt.approx.f32 %0, %1;" : "=f"(r) : "f"(x));
    return r;
}

__global__ void __launch_bounds__(T2) pass2_kernel(const float* __restrict__ emb,
                                                   const int* __restrict__ mask) {
    __shared__ float4 cs4[(KK + 1) * 2];   // centers table, float4-aligned
    __shared__ float vacc[T2 * VSLOT];
    const int t = threadIdx.x;
    const int b = blockIdx.y;

    if (t < (KK + 1) * DD) {
        const int slot = t / DD, d = t % DD;
        float v = 0.f;
        if (slot >= 1)
            v = g_sums[b][slot - 1][d] / fmaxf((float)g_cnt[b][slot], 1.f);
        reinterpret_cast<float*>(cs4)[t] = v;
    }
#pragma unroll
    for (int j = 0; j < VSLOT; j++) vacc[t * VSLOT + j] = 0.f;
    __syncthreads();

    const float* eb = emb + (size_t)b * DD * PP;
    const int*   mb = mask + (size_t)b * PP;
    const int stride = GX2 * T2 * 4;

    for (int p0 = (blockIdx.x * T2 + t) * 4; p0 < PP; p0 += stride) {
        const int4 lab4 = *reinterpret_cast<const int4*>(mb + p0);
        float ev[4][DD];
#pragma unroll
        for (int d = 0; d < DD; d++) {
            float4 v = *reinterpret_cast<const float4*>(eb + (size_t)d * PP + p0);
            ev[0][d] = v.x; ev[1][d] = v.y; ev[2][d] = v.z; ev[3][d] = v.w;
        }
        int labs[4] = {lab4.x, lab4.y, lab4.z, lab4.w};
#pragma unroll
        for (int i = 0; i < 4; i++) {
            const int lab = labs[i];
            const float4 clo = cs4[lab * 2];
            const float4 chi = cs4[lab * 2 + 1];
            float d0 = ev[i][0] - clo.x;
            float s  = d0 * d0;
            float d1 = ev[i][1] - clo.y; s = fmaf(d1, d1, s);
            float d2 = ev[i][2] - clo.z; s = fmaf(d2, d2, s);
            float d3 = ev[i][3] - clo.w; s = fmaf(d3, d3, s);
            float d4 = ev[i][4] - chi.x; s = fmaf(d4, d4, s);
            float d5 = ev[i][5] - chi.y; s = fmaf(d5, d5, s);
            float d6 = ev[i][6] - chi.z; s = fmaf(d6, d6, s);
            float d7 = ev[i][7] - chi.w; s = fmaf(d7, d7, s);
            // max(sqrt(s)-0.5,0)^2 == s - sqrt(s) + 0.25 when s > 0.25 else 0
            float val = (s - fsqrt_approx(s)) + 0.25f;
            val = (s > 0.25f) ? val : 0.f;
            vacc[t * VSLOT + lab] += val;
        }
    }

    __syncthreads();
    for (int off = T2 / 2; off > 0; off >>= 1) {
        if (t < off) {
            float* a = vacc + t * VSLOT;
            float* c = vacc + (t + off) * VSLOT;
#pragma unroll
            for (int j = 0; j < 6; j++) a[j] += c[j];
        }
        __syncthreads();
    }
    if (t >= 1 && t <= KK) atomicAdd(&g_var[b][t], vacc[t]);
}

// ---------------------------------------------------------------------------
// Finalize: cooperative smem preload of all scratch, per-b epilogue, output
// write, and scratch reset for the next graph replay.
#define TF 320

__global__ void __launch_bounds__(TF) finalize_kernel(float* __restrict__ out) {
    __shared__ float sh_sums[BB][KK][DD];
    __shared__ float sh_cnt[BB][KK + 1];
    __shared__ float sh_varr[BB][KK + 1];
    __shared__ float s_var[BB], s_dist[BB], s_reg[BB], s_has[BB];
    const int t = threadIdx.x;

    if (t < BB * KK * DD) (&sh_sums[0][0][0])[t] = (&g_sums[0][0][0])[t];
    if (t < BB * (KK + 1)) {
        (&sh_cnt[0][0])[t]  = (float)(&g_cnt[0][0])[t];
        (&sh_varr[0][0])[t] = (&g_var[0][0])[t];
    }
    __syncthreads();

    if (t < BB) {
        const int b = t;
        float cnt[KK], present[KK], N = 0.f;
        float ctr[KK][DD];
#pragma unroll
        for (int k = 0; k < KK; k++) {
            cnt[k] = sh_cnt[b][k + 1];
            present[k] = cnt[k] > 0.f ? 1.f : 0.f;
            N += present[k];
            const float inv = 1.f / fmaxf(cnt[k], 1.f);
#pragma unroll
            for (int d = 0; d < DD; d++) ctr[k][d] = sh_sums[b][k][d] * inv;
        }
        float lv = 0.f;
#pragma unroll
        for (int k = 0; k < KK; k++)
            lv += present[k] * (sh_varr[b][k + 1] / fmaxf(cnt[k], 1.f));
        lv /= fmaxf(N, 1.f);

        float ld = 0.f;
        for (int i = 0; i < KK; i++) {
            for (int j = i + 1; j < KK; j++) {
                if (present[i] > 0.f && present[j] > 0.f) {
                    float dsq = 0.f;
#pragma unroll
                    for (int d = 0; d < DD; d++) {
                        float df = ctr[i][d] - ctr[j][d];
                        dsq = fmaf(df, df, dsq);
                    }
                    float dist = sqrtf(dsq);
                    float term = fmaxf(6.0f - dist, 0.f);  // 2*DELTA_D = 6
                    ld += term * term;
                }
            }
        }
        float npairs = N * (N - 1.f) * 0.5f;
        ld /= (N > 1.f) ? npairs : 1.f;

        float lr = 0.f;
#pragma unroll
        for (int k = 0; k < KK; k++) {
            if (present[k] > 0.f) {
                float nsq = 0.f;
#pragma unroll
                for (int d = 0; d < DD; d++) {
                    float c = ctr[k][d];
                    nsq = fmaf(c, c, nsq);
                }
                lr += sqrtf(nsq);
            }
        }
        lr /= fmaxf(N, 1.f);
        s_var[b] = lv; s_dist[b] = ld; s_reg[b] = lr;
        s_has[b] = (N > 0.f) ? 1.f : 0.f;
    }
    __syncthreads();
    if (t == 0) {
        float hv = 0.f, hd = 0.f, hr = 0.f, hh = 0.f;
#pragma unroll
        for (int b = 0; b < BB; b++) {
            hh += s_has[b];
            hv += s_var[b] * s_has[b];
            hd += s_dist[b] * s_has[b];
            hr += s_reg[b] * s_has[b];
        }
        const float den = fmaxf(hh, 1.f);
        const float var = hv / den, dist = hd / den, reg = hr / den;
        out[0] = var + dist + 0.001f * reg;  // ALPHA=BETA=1, GAMMA=0.001
        out[1] = var;
        out[2] = dist;
        out[3] = reg;
    }

    // reset scratch for the next graph replay
    if (t < BB * KK * DD) (&g_sums[0][0][0])[t] = 0.f;
    if (t < BB * (KK + 1)) {
        (&g_cnt[0][0])[t] = 0;
        (&g_var[0][0])[t] = 0.f;
    }
}

// ---------------------------------------------------------------------------
extern "C" void kernel_launch(void* const* d_in, const int* in_sizes, int n_in,
                              void* d_out, int out_size) {
    const float* emb  = (const float*)d_in[0];
    const int*   mask = (const int*)d_in[1];
    float*       out  = (float*)d_out;

    dim3 g1(GX1, BB);
    pass1_kernel<<<g1, T1>>>(emb, mask);
    dim3 g2(GX2, BB);
    pass2_kernel<<<g2, T2>>>(emb, mask);
    finalize_kernel<<<1, TF>>>(out);
}

// round 12
// speedup vs baseline: 1.8312x; 1.1705x over previous
#include <cuda_runtime.h>
#include <cstdint>

#define BB 8
#define DD 8
#define KK 5
#define PP (512*1024)

// ---- scratch (device globals; zero-initialized at module load; finalize
// resets them at the end of every run so graph replays start clean) ----
__device__ float g_sums[BB][KK][DD];   // per-batch per-instance channel sums
__device__ int   g_cnt[BB][KK + 1];    // per-batch per-slot pixel counts
__device__ float g_var[BB][KK + 1];    // per-batch per-slot variance sums

// ---------------------------------------------------------------------------
// Pass 1: 4 channels per thread, select-based (NO branches in the hot loop).
// Block = 8 warps: warp w covers pixel-quarter (w&3) and channel group
// (w>>2)*4 .. +3. Per pixel: 5 ISETP+SEL masks shared across 4 FFMAs each.
#define T1 256
#define GX1 512
#define ITER1 2
// coverage: GX1 blocks * 4 quarters * 32 lanes * 4 px * ITER1 = 524288 = PP

__global__ void __launch_bounds__(T1) pass1_kernel(const float* __restrict__ emb,
                                                   const int* __restrict__ mask) {
    __shared__ float red[8][KK * 4];
    const int t = threadIdx.x;
    const int b = blockIdx.y;
    const int w = t >> 5, lane = t & 31;
    const int q = w & 3;        // pixel quarter
    const int g = w >> 2;       // channel group (0: ch0-3, 1: ch4-7)

    float acc[KK][4];
#pragma unroll
    for (int k = 0; k < KK; k++)
#pragma unroll
        for (int j = 0; j < 4; j++) acc[k][j] = 0.f;
    unsigned long long cnt64 = 0ull;

    const float* ep = emb + (size_t)b * DD * PP + (size_t)(g * 4) * PP;
    const int*   mb = mask + (size_t)b * PP;
    int p = ((blockIdx.x * 4 + q) * 32 + lane) * 4;
    const int stride = GX1 * 4 * 32 * 4;

#pragma unroll
    for (int it = 0; it < ITER1; it++, p += stride) {
        const int4 lab4 = *reinterpret_cast<const int4*>(mb + p);
        const float4 v0 = *reinterpret_cast<const float4*>(ep + 0 * (size_t)PP + p);
        const float4 v1 = *reinterpret_cast<const float4*>(ep + 1 * (size_t)PP + p);
        const float4 v2 = *reinterpret_cast<const float4*>(ep + 2 * (size_t)PP + p);
        const float4 v3 = *reinterpret_cast<const float4*>(ep + 3 * (size_t)PP + p);
        const float ev[4][4] = {
            {v0.x, v1.x, v2.x, v3.x},
            {v0.y, v1.y, v2.y, v3.y},
            {v0.z, v1.z, v2.z, v3.z},
            {v0.w, v1.w, v2.w, v3.w}};
        const int labs[4] = {lab4.x, lab4.y, lab4.z, lab4.w};
#pragma unroll
        for (int i = 0; i < 4; i++) {
            const int lab = labs[i];
            if (g == 0) cnt64 += 1ull << (lab * 8);   // uniform per warp: no divergence
#pragma unroll
            for (int k = 0; k < KK; k++) {
                const float m = (lab == k + 1) ? 1.f : 0.f;
#pragma unroll
                for (int j = 0; j < 4; j++)
                    acc[k][j] = fmaf(m, ev[i][j], acc[k][j]);
            }
        }
    }

    // warp-shuffle reduce the 20 accumulators
#pragma unroll
    for (int off = 16; off > 0; off >>= 1) {
#pragma unroll
        for (int k = 0; k < KK; k++)
#pragma unroll
            for (int j = 0; j < 4; j++)
                acc[k][j] += __shfl_down_sync(0xffffffffu, acc[k][j], off);
    }
    if (lane == 0) {
#pragma unroll
        for (int k = 0; k < KK; k++)
#pragma unroll
            for (int j = 0; j < 4; j++)
                red[w][k * 4 + j] = acc[k][j];
    }
    __syncthreads();
    if (t < KK * DD) {
        const int k = t >> 3, d = t & 7;          // g_sums layout [k][d]
        const int gg = d >> 2, j = d & 3;
        float s = 0.f;
#pragma unroll
        for (int wq = 0; wq < 4; wq++) s += red[gg * 4 + wq][k * 4 + j];
        atomicAdd(&g_sums[b][k][d], s);
    }

    // counts from channel-group-0 warps (each covers its own pixel quarter)
    if (g == 0) {
#pragma unroll
        for (int k = 1; k <= KK; k++) {
            unsigned c = (unsigned)((cnt64 >> (8 * k)) & 0xffull);
            c = __reduce_add_sync(0xffffffffu, c);
            if (lane == 0) atomicAdd(&g_cnt[b][k], (int)c);
        }
    }
}

// ---------------------------------------------------------------------------
// Pass 2: per-pixel hinge-variance term (smem per-thread slots for the 6
// label accumulators), centers computed inline in the prologue.
#define T2 256
#define VSLOT 9
#define GX2 128

__device__ __forceinline__ float fsqrt_approx(float x) {
    float r;
    asm("sqrt.approx.f32 %0, %1;" : "=f"(r) : "f"(x));
    return r;
}

__global__ void __launch_bounds__(T2) pass2_kernel(const float* __restrict__ emb,
                                                   const int* __restrict__ mask) {
    __shared__ float4 cs4[(KK + 1) * 2];   // centers table, float4-aligned
    __shared__ float vacc[T2 * VSLOT];
    const int t = threadIdx.x;
    const int b = blockIdx.y;

    if (t < (KK + 1) * DD) {
        const int slot = t / DD, d = t % DD;
        float v = 0.f;
        if (slot >= 1)
            v = g_sums[b][slot - 1][d] / fmaxf((float)g_cnt[b][slot], 1.f);
        reinterpret_cast<float*>(cs4)[t] = v;
    }
#pragma unroll
    for (int j = 0; j < VSLOT; j++) vacc[t * VSLOT + j] = 0.f;
    __syncthreads();

    const float* eb = emb + (size_t)b * DD * PP;
    const int*   mb = mask + (size_t)b * PP;
    const int stride = GX2 * T2 * 4;

    for (int p0 = (blockIdx.x * T2 + t) * 4; p0 < PP; p0 += stride) {
        const int4 lab4 = *reinterpret_cast<const int4*>(mb + p0);
        float ev[4][DD];
#pragma unroll
        for (int d = 0; d < DD; d++) {
            float4 v = *reinterpret_cast<const float4*>(eb + (size_t)d * PP + p0);
            ev[0][d] = v.x; ev[1][d] = v.y; ev[2][d] = v.z; ev[3][d] = v.w;
        }
        int labs[4] = {lab4.x, lab4.y, lab4.z, lab4.w};
#pragma unroll
        for (int i = 0; i < 4; i++) {
            const int lab = labs[i];
            const float4 clo = cs4[lab * 2];
            const float4 chi = cs4[lab * 2 + 1];
            float d0 = ev[i][0] - clo.x;
            float s  = d0 * d0;
            float d1 = ev[i][1] - clo.y; s = fmaf(d1, d1, s);
            float d2 = ev[i][2] - clo.z; s = fmaf(d2, d2, s);
            float d3 = ev[i][3] - clo.w; s = fmaf(d3, d3, s);
            float d4 = ev[i][4] - chi.x; s = fmaf(d4, d4, s);
            float d5 = ev[i][5] - chi.y; s = fmaf(d5, d5, s);
            float d6 = ev[i][6] - chi.z; s = fmaf(d6, d6, s);
            float d7 = ev[i][7] - chi.w; s = fmaf(d7, d7, s);
            // max(sqrt(s)-0.5,0)^2 == s - sqrt(s) + 0.25 when s > 0.25 else 0
            float val = (s - fsqrt_approx(s)) + 0.25f;
            val = (s > 0.25f) ? val : 0.f;
            vacc[t * VSLOT + lab] += val;
        }
    }

    __syncthreads();
    for (int off = T2 / 2; off > 0; off >>= 1) {
        if (t < off) {
            float* a = vacc + t * VSLOT;
            float* c = vacc + (t + off) * VSLOT;
#pragma unroll
            for (int j = 0; j < 6; j++) a[j] += c[j];
        }
        __syncthreads();
    }
    if (t >= 1 && t <= KK) atomicAdd(&g_var[b][t], vacc[t]);
}

// ---------------------------------------------------------------------------
// Finalize: cooperative smem preload of all scratch, per-b epilogue, output
// write, and scratch reset for the next graph replay.
#define TF 320

__global__ void __launch_bounds__(TF) finalize_kernel(float* __restrict__ out) {
    __shared__ float sh_sums[BB][KK][DD];
    __shared__ float sh_cnt[BB][KK + 1];
    __shared__ float sh_varr[BB][KK + 1];
    __shared__ float s_var[BB], s_dist[BB], s_reg[BB], s_has[BB];
    const int t = threadIdx.x;

    if (t < BB * KK * DD) (&sh_sums[0][0][0])[t] = (&g_sums[0][0][0])[t];
    if (t < BB * (KK + 1)) {
        (&sh_cnt[0][0])[t]  = (float)(&g_cnt[0][0])[t];
        (&sh_varr[0][0])[t] = (&g_var[0][0])[t];
    }
    __syncthreads();

    if (t < BB) {
        const int b = t;
        float cnt[KK], present[KK], N = 0.f;
        float ctr[KK][DD];
#pragma unroll
        for (int k = 0; k < KK; k++) {
            cnt[k] = sh_cnt[b][k + 1];
            present[k] = cnt[k] > 0.f ? 1.f : 0.f;
            N += present[k];
            const float inv = 1.f / fmaxf(cnt[k], 1.f);
#pragma unroll
            for (int d = 0; d < DD; d++) ctr[k][d] = sh_sums[b][k][d] * inv;
        }
        float lv = 0.f;
#pragma unroll
        for (int k = 0; k < KK; k++)
            lv += present[k] * (sh_varr[b][k + 1] / fmaxf(cnt[k], 1.f));
        lv /= fmaxf(N, 1.f);

        float ld = 0.f;
        for (int i = 0; i < KK; i++) {
            for (int j = i + 1; j < KK; j++) {
                if (present[i] > 0.f && present[j] > 0.f) {
                    float dsq = 0.f;
#pragma unroll
                    for (int d = 0; d < DD; d++) {
                        float df = ctr[i][d] - ctr[j][d];
                        dsq = fmaf(df, df, dsq);
                    }
                    float dist = sqrtf(dsq);
                    float term = fmaxf(6.0f - dist, 0.f);  // 2*DELTA_D = 6
                    ld += term * term;
                }
            }
        }
        float npairs = N * (N - 1.f) * 0.5f;
        ld /= (N > 1.f) ? npairs : 1.f;

        float lr = 0.f;
#pragma unroll
        for (int k = 0; k < KK; k++) {
            if (present[k] > 0.f) {
                float nsq = 0.f;
#pragma unroll
                for (int d = 0; d < DD; d++) {
                    float c = ctr[k][d];
                    nsq = fmaf(c, c, nsq);
                }
                lr += sqrtf(nsq);
            }
        }
        lr /= fmaxf(N, 1.f);
        s_var[b] = lv; s_dist[b] = ld; s_reg[b] = lr;
        s_has[b] = (N > 0.f) ? 1.f : 0.f;
    }
    __syncthreads();
    if (t == 0) {
        float hv = 0.f, hd = 0.f, hr = 0.f, hh = 0.f;
#pragma unroll
        for (int b = 0; b < BB; b++) {
            hh += s_has[b];
            hv += s_var[b] * s_has[b];
            hd += s_dist[b] * s_has[b];
            hr += s_reg[b] * s_has[b];
        }
        const float den = fmaxf(hh, 1.f);
        const float var = hv / den, dist = hd / den, reg = hr / den;
        out[0] = var + dist + 0.001f * reg;  // ALPHA=BETA=1, GAMMA=0.001
        out[1] = var;
        out[2] = dist;
        out[3] = reg;
    }

    // reset scratch for the next graph replay
    if (t < BB * KK * DD) (&g_sums[0][0][0])[t] = 0.f;
    if (t < BB * (KK + 1)) {
        (&g_cnt[0][0])[t] = 0;
        (&g_var[0][0])[t] = 0.f;
    }
}

// ---------------------------------------------------------------------------
extern "C" void kernel_launch(void* const* d_in, const int* in_sizes, int n_in,
                              void* d_out, int out_size) {
    const float* emb  = (const float*)d_in[0];
    const int*   mask = (const int*)d_in[1];
    float*       out  = (float*)d_out;

    dim3 g1(GX1, BB);
    pass1_kernel<<<g1, T1>>>(emb, mask);
    dim3 g2(GX2, BB);
    pass2_kernel<<<g2, T2>>>(emb, mask);
    finalize_kernel<<<1, TF>>>(out);
}

// round 13
// speedup vs baseline: 1.9059x; 1.0408x over previous
#include <cuda_runtime.h>
#include <cstdint>

#define BB 8
#define DD 8
#define KK 5
#define PP (512*1024)

// ---- scratch (device globals; zero-initialized at module load; finalize
// resets them at the end of every run so graph replays start clean) ----
__device__ float g_sums[BB][KK][DD];   // per-batch per-instance channel sums
__device__ int   g_cnt[BB][KK + 1];    // per-batch per-slot pixel counts
__device__ float g_var[BB][KK + 1];    // per-batch per-slot variance sums

// ---------------------------------------------------------------------------
// Pass 1: channel-split with REGISTER accumulators (round-8 proven shape).
// Warp w of each block owns channel plane w; all 8 warps sweep the same pixel
// window (mask int4 loads dedupe in L1). Accumulation via forced predication:
// 5 setp + 5 @p add.f32 per pixel-channel (inline PTX; no FSEL, no branches).
#define T1 256
#define GX1 512
#define ITER1 8
// coverage: GX1 * 32 lanes * 4 px * ITER1 = 524288 = PP exactly

__device__ __forceinline__ void acc_label(float* acc, float e, int lab) {
    asm volatile(
        "{\n\t"
        ".reg .pred p1,p2,p3,p4,p5;\n\t"
        "setp.eq.s32 p1, %6, 1;\n\t"
        "setp.eq.s32 p2, %6, 2;\n\t"
        "setp.eq.s32 p3, %6, 3;\n\t"
        "setp.eq.s32 p4, %6, 4;\n\t"
        "setp.eq.s32 p5, %6, 5;\n\t"
        "@p1 add.f32 %0, %0, %5;\n\t"
        "@p2 add.f32 %1, %1, %5;\n\t"
        "@p3 add.f32 %2, %2, %5;\n\t"
        "@p4 add.f32 %3, %3, %5;\n\t"
        "@p5 add.f32 %4, %4, %5;\n\t"
        "}"
        : "+f"(acc[0]), "+f"(acc[1]), "+f"(acc[2]), "+f"(acc[3]), "+f"(acc[4])
        : "f"(e), "r"(lab));
}

__global__ void __launch_bounds__(T1) pass1_kernel(const float* __restrict__ emb,
                                                   const int* __restrict__ mask) {
    __shared__ float red[DD][KK];
    const int t = threadIdx.x;
    const int b = blockIdx.y;
    const int w = t >> 5, lane = t & 31;   // w = channel index

    float acc[KK];
#pragma unroll
    for (int k = 0; k < KK; k++) acc[k] = 0.f;

    unsigned long long cnt64 = 0ull;
    const float* ep = emb + (size_t)b * DD * PP + (size_t)w * PP;
    const int*   mb = mask + (size_t)b * PP;
    int p = (blockIdx.x * 32 + lane) * 4;
    const int stride = GX1 * 32 * 4;

#pragma unroll
    for (int it = 0; it < ITER1; it++, p += stride) {
        const int4 lab4 = *reinterpret_cast<const int4*>(mb + p);
        const float4 v  = *reinterpret_cast<const float4*>(ep + p);
        const int labs[4] = {lab4.x, lab4.y, lab4.z, lab4.w};
        const float es[4] = {v.x, v.y, v.z, v.w};
#pragma unroll
        for (int i = 0; i < 4; i++) {
            const int lab = labs[i];
            if (w == 0) cnt64 += 1ull << (lab * 8);   // warp-uniform predicate
            acc_label(acc, es[i], lab);
        }
    }

    // per-warp reduction: 5 instance sums for channel w
#pragma unroll
    for (int off = 16; off > 0; off >>= 1) {
#pragma unroll
        for (int k = 0; k < KK; k++)
            acc[k] += __shfl_down_sync(0xffffffffu, acc[k], off);
    }
    if (lane == 0) {
#pragma unroll
        for (int k = 0; k < KK; k++) red[w][k] = acc[k];
    }
    __syncthreads();
    if (t < KK * DD) {
        const int k = t >> 3, d = t & 7;        // g_sums layout [k][d]
        atomicAdd(&g_sums[b][k][d], red[d][k]);
    }

    // counts from warp 0 only (each label count <= 32 fits a byte)
    if (w == 0) {
#pragma unroll
        for (int k = 1; k <= KK; k++) {
            unsigned c = (unsigned)((cnt64 >> (8 * k)) & 0xffull);
            c = __reduce_add_sync(0xffffffffu, c);
            if (lane == 0) atomicAdd(&g_cnt[b][k], (int)c);
        }
    }
}

// ---------------------------------------------------------------------------
// Pass 2: per-pixel hinge-variance term (smem per-thread slots for the 6
// label accumulators), centers computed inline in the prologue.
#define T2 256
#define VSLOT 9
#define GX2 128

__device__ __forceinline__ float fsqrt_approx(float x) {
    float r;
    asm("sqrt.approx.f32 %0, %1;" : "=f"(r) : "f"(x));
    return r;
}

__global__ void __launch_bounds__(T2) pass2_kernel(const float* __restrict__ emb,
                                                   const int* __restrict__ mask) {
    __shared__ float4 cs4[(KK + 1) * 2];   // centers table, float4-aligned
    __shared__ float vacc[T2 * VSLOT];
    const int t = threadIdx.x;
    const int b = blockIdx.y;

    if (t < (KK + 1) * DD) {
        const int slot = t / DD, d = t % DD;
        float v = 0.f;
        if (slot >= 1)
            v = g_sums[b][slot - 1][d] / fmaxf((float)g_cnt[b][slot], 1.f);
        reinterpret_cast<float*>(cs4)[t] = v;
    }
#pragma unroll
    for (int j = 0; j < VSLOT; j++) vacc[t * VSLOT + j] = 0.f;
    __syncthreads();

    const float* eb = emb + (size_t)b * DD * PP;
    const int*   mb = mask + (size_t)b * PP;
    const int stride = GX2 * T2 * 4;

    for (int p0 = (blockIdx.x * T2 + t) * 4; p0 < PP; p0 += stride) {
        const int4 lab4 = *reinterpret_cast<const int4*>(mb + p0);
        float ev[4][DD];
#pragma unroll
        for (int d = 0; d < DD; d++) {
            float4 v = *reinterpret_cast<const float4*>(eb + (size_t)d * PP + p0);
            ev[0][d] = v.x; ev[1][d] = v.y; ev[2][d] = v.z; ev[3][d] = v.w;
        }
        int labs[4] = {lab4.x, lab4.y, lab4.z, lab4.w};
#pragma unroll
        for (int i = 0; i < 4; i++) {
            const int lab = labs[i];
            const float4 clo = cs4[lab * 2];
            const float4 chi = cs4[lab * 2 + 1];
            float d0 = ev[i][0] - clo.x;
            float s  = d0 * d0;
            float d1 = ev[i][1] - clo.y; s = fmaf(d1, d1, s);
            float d2 = ev[i][2] - clo.z; s = fmaf(d2, d2, s);
            float d3 = ev[i][3] - clo.w; s = fmaf(d3, d3, s);
            float d4 = ev[i][4] - chi.x; s = fmaf(d4, d4, s);
            float d5 = ev[i][5] - chi.y; s = fmaf(d5, d5, s);
            float d6 = ev[i][6] - chi.z; s = fmaf(d6, d6, s);
            float d7 = ev[i][7] - chi.w; s = fmaf(d7, d7, s);
            // max(sqrt(s)-0.5,0)^2 == s - sqrt(s) + 0.25 when s > 0.25 else 0
            float val = (s - fsqrt_approx(s)) + 0.25f;
            val = (s > 0.25f) ? val : 0.f;
            vacc[t * VSLOT + lab] += val;
        }
    }

    __syncthreads();
    for (int off = T2 / 2; off > 0; off >>= 1) {
        if (t < off) {
            float* a = vacc + t * VSLOT;
            float* c = vacc + (t + off) * VSLOT;
#pragma unroll
            for (int j = 0; j < 6; j++) a[j] += c[j];
        }
        __syncthreads();
    }
    if (t >= 1 && t <= KK) atomicAdd(&g_var[b][t], vacc[t]);
}

// ---------------------------------------------------------------------------
// Finalize: cooperative smem preload of all scratch, per-b epilogue, output
// write, and scratch reset for the next graph replay.
#define TF 320

__global__ void __launch_bounds__(TF) finalize_kernel(float* __restrict__ out) {
    __shared__ float sh_sums[BB][KK][DD];
    __shared__ float sh_cnt[BB][KK + 1];
    __shared__ float sh_varr[BB][KK + 1];
    __shared__ float s_var[BB], s_dist[BB], s_reg[BB], s_has[BB];
    const int t = threadIdx.x;

    if (t < BB * KK * DD) (&sh_sums[0][0][0])[t] = (&g_sums[0][0][0])[t];
    if (t < BB * (KK + 1)) {
        (&sh_cnt[0][0])[t]  = (float)(&g_cnt[0][0])[t];
        (&sh_varr[0][0])[t] = (&g_var[0][0])[t];
    }
    __syncthreads();

    if (t < BB) {
        const int b = t;
        float cnt[KK], present[KK], N = 0.f;
        float ctr[KK][DD];
#pragma unroll
        for (int k = 0; k < KK; k++) {
            cnt[k] = sh_cnt[b][k + 1];
            present[k] = cnt[k] > 0.f ? 1.f : 0.f;
            N += present[k];
            const float inv = 1.f / fmaxf(cnt[k], 1.f);
#pragma unroll
            for (int d = 0; d < DD; d++) ctr[k][d] = sh_sums[b][k][d] * inv;
        }
        float lv = 0.f;
#pragma unroll
        for (int k = 0; k < KK; k++)
            lv += present[k] * (sh_varr[b][k + 1] / fmaxf(cnt[k], 1.f));
        lv /= fmaxf(N, 1.f);

        float ld = 0.f;
        for (int i = 0; i < KK; i++) {
            for (int j = i + 1; j < KK; j++) {
                if (present[i] > 0.f && present[j] > 0.f) {
                    float dsq = 0.f;
#pragma unroll
                    for (int d = 0; d < DD; d++) {
                        float df = ctr[i][d] - ctr[j][d];
                        dsq = fmaf(df, df, dsq);
                    }
                    float dist = sqrtf(dsq);
                    float term = fmaxf(6.0f - dist, 0.f);  // 2*DELTA_D = 6
                    ld += term * term;
                }
            }
        }
        float npairs = N * (N - 1.f) * 0.5f;
        ld /= (N > 1.f) ? npairs : 1.f;

        float lr = 0.f;
#pragma unroll
        for (int k = 0; k < KK; k++) {
            if (present[k] > 0.f) {
                float nsq = 0.f;
#pragma unroll
                for (int d = 0; d < DD; d++) {
                    float c = ctr[k][d];
                    nsq = fmaf(c, c, nsq);
                }
                lr += sqrtf(nsq);
            }
        }
        lr /= fmaxf(N, 1.f);
        s_var[b] = lv; s_dist[b] = ld; s_reg[b] = lr;
        s_has[b] = (N > 0.f) ? 1.f : 0.f;
    }
    __syncthreads();
    if (t == 0) {
        float hv = 0.f, hd = 0.f, hr = 0.f, hh = 0.f;
#pragma unroll
        for (int b = 0; b < BB; b++) {
            hh += s_has[b];
            hv += s_var[b] * s_has[b];
            hd += s_dist[b] * s_has[b];
            hr += s_reg[b] * s_has[b];
        }
        const float den = fmaxf(hh, 1.f);
        const float var = hv / den, dist = hd / den, reg = hr / den;
        out[0] = var + dist + 0.001f * reg;  // ALPHA=BETA=1, GAMMA=0.001
        out[1] = var;
        out[2] = dist;
        out[3] = reg;
    }

    // reset scratch for the next graph replay
    if (t < BB * KK * DD) (&g_sums[0][0][0])[t] = 0.f;
    if (t < BB * (KK + 1)) {
        (&g_cnt[0][0])[t] = 0;
        (&g_var[0][0])[t] = 0.f;
    }
}

// ---------------------------------------------------------------------------
extern "C" void kernel_launch(void* const* d_in, const int* in_sizes, int n_in,
                              void* d_out, int out_size) {
    const float* emb  = (const float*)d_in[0];
    const int*   mask = (const int*)d_in[1];
    float*       out  = (float*)d_out;

    dim3 g1(GX1, BB);
    pass1_kernel<<<g1, T1>>>(emb, mask);
    dim3 g2(GX2, BB);
    pass2_kernel<<<g2, T2>>>(emb, mask);
    finalize_kernel<<<1, TF>>>(out);
}

// round 14
// speedup vs baseline: 2.6618x; 1.3966x over previous
#include <cuda_runtime.h>
#include <cstdint>

#define BB 8
#define DD 8
#define KK 5
#define PP (512*1024)

// ---- scratch (device globals; zero-initialized at module load; finalize
// resets them at the end of every run so graph replays start clean) ----
__device__ float g_sums[BB][KK][DD];   // per-batch per-instance channel sums
__device__ int   g_cnt[BB][KK + 1];    // per-batch per-slot pixel counts
__device__ float g_var[BB][KK + 1];    // per-batch per-slot variance sums

// ---------------------------------------------------------------------------
// Pass 1: channel-split with REGISTER accumulators (round-8 proven shape).
// Warp w of each block owns channel plane w; all 8 warps sweep the same pixel
// window (mask int4 loads dedupe in L1). Accumulate via the predication-
// friendly ternary-on-accumulator form: ISETP + @p FADD per label.
#define T1 256
#define GX1 512
#define ITER1 8
// coverage: GX1 * 32 lanes * 4 px * ITER1 = 524288 = PP exactly

__global__ void __launch_bounds__(T1) pass1_kernel(const float* __restrict__ emb,
                                                   const int* __restrict__ mask) {
    __shared__ float red[DD][KK];
    const int t = threadIdx.x;
    const int b = blockIdx.y;
    const int w = t >> 5, lane = t & 31;   // w = channel index

    float acc[KK];
#pragma unroll
    for (int k = 0; k < KK; k++) acc[k] = 0.f;

    unsigned long long cnt64 = 0ull;
    const float* ep = emb + (size_t)b * DD * PP + (size_t)w * PP;
    const int*   mb = mask + (size_t)b * PP;
    int p = (blockIdx.x * 32 + lane) * 4;
    const int stride = GX1 * 32 * 4;

#pragma unroll
    for (int it = 0; it < ITER1; it++, p += stride) {
        const int4 lab4 = *reinterpret_cast<const int4*>(mb + p);
        const float4 v  = *reinterpret_cast<const float4*>(ep + p);
        const int labs[4] = {lab4.x, lab4.y, lab4.z, lab4.w};
        const float es[4] = {v.x, v.y, v.z, v.w};
#pragma unroll
        for (int i = 0; i < 4; i++) {
            const int lab = labs[i];
            if (w == 0) cnt64 += 1ull << (lab * 8);   // warp-uniform predicate
#pragma unroll
            for (int k = 0; k < KK; k++)
                acc[k] = (lab == k + 1) ? acc[k] + es[i] : acc[k];
        }
    }

    // per-warp reduction: 5 instance sums for channel w
#pragma unroll
    for (int off = 16; off > 0; off >>= 1) {
#pragma unroll
        for (int k = 0; k < KK; k++)
            acc[k] += __shfl_down_sync(0xffffffffu, acc[k], off);
    }
    if (lane == 0) {
#pragma unroll
        for (int k = 0; k < KK; k++) red[w][k] = acc[k];
    }
    __syncthreads();
    if (t < KK * DD) {
        const int k = t >> 3, d = t & 7;        // g_sums layout [k][d]
        atomicAdd(&g_sums[b][k][d], red[d][k]);
    }

    // counts from warp 0 only (each label count <= 32 fits a byte)
    if (w == 0) {
#pragma unroll
        for (int k = 1; k <= KK; k++) {
            unsigned c = (unsigned)((cnt64 >> (8 * k)) & 0xffull);
            c = __reduce_add_sync(0xffffffffu, c);
            if (lane == 0) atomicAdd(&g_cnt[b][k], (int)c);
        }
    }
}

// ---------------------------------------------------------------------------
// Pass 2: per-pixel hinge-variance term (smem per-thread slots for the 6
// label accumulators), centers computed inline in the prologue.
#define T2 256
#define VSLOT 9
#define GX2 256

__device__ __forceinline__ float fsqrt_approx(float x) {
    float r;
    asm("sqrt.approx.f32 %0, %1;" : "=f"(r) : "f"(x));
    return r;
}

__global__ void __launch_bounds__(T2) pass2_kernel(const float* __restrict__ emb,
                                                   const int* __restrict__ mask) {
    __shared__ float4 cs4[(KK + 1) * 2];   // centers table, float4-aligned
    __shared__ float vacc[T2 * VSLOT];
    const int t = threadIdx.x;
    const int b = blockIdx.y;

    if (t < (KK + 1) * DD) {
        const int slot = t / DD, d = t % DD;
        float v = 0.f;
        if (slot >= 1)
            v = g_sums[b][slot - 1][d] / fmaxf((float)g_cnt[b][slot], 1.f);
        reinterpret_cast<float*>(cs4)[t] = v;
    }
#pragma unroll
    for (int j = 0; j < VSLOT; j++) vacc[t * VSLOT + j] = 0.f;
    __syncthreads();

    const float* eb = emb + (size_t)b * DD * PP;
    const int*   mb = mask + (size_t)b * PP;
    const int stride = GX2 * T2 * 4;

    for (int p0 = (blockIdx.x * T2 + t) * 4; p0 < PP; p0 += stride) {
        const int4 lab4 = *reinterpret_cast<const int4*>(mb + p0);
        float ev[4][DD];
#pragma unroll
        for (int d = 0; d < DD; d++) {
            float4 v = *reinterpret_cast<const float4*>(eb + (size_t)d * PP + p0);
            ev[0][d] = v.x; ev[1][d] = v.y; ev[2][d] = v.z; ev[3][d] = v.w;
        }
        int labs[4] = {lab4.x, lab4.y, lab4.z, lab4.w};
#pragma unroll
        for (int i = 0; i < 4; i++) {
            const int lab = labs[i];
            const float4 clo = cs4[lab * 2];
            const float4 chi = cs4[lab * 2 + 1];
            float d0 = ev[i][0] - clo.x;
            float s  = d0 * d0;
            float d1 = ev[i][1] - clo.y; s = fmaf(d1, d1, s);
            float d2 = ev[i][2] - clo.z; s = fmaf(d2, d2, s);
            float d3 = ev[i][3] - clo.w; s = fmaf(d3, d3, s);
            float d4 = ev[i][4] - chi.x; s = fmaf(d4, d4, s);
            float d5 = ev[i][5] - chi.y; s = fmaf(d5, d5, s);
            float d6 = ev[i][6] - chi.z; s = fmaf(d6, d6, s);
            float d7 = ev[i][7] - chi.w; s = fmaf(d7, d7, s);
            // max(sqrt(s)-0.5,0)^2 == s - sqrt(s) + 0.25 when s > 0.25 else 0
            float val = (s - fsqrt_approx(s)) + 0.25f;
            val = (s > 0.25f) ? val : 0.f;
            vacc[t * VSLOT + lab] += val;
        }
    }

    __syncthreads();
    for (int off = T2 / 2; off > 0; off >>= 1) {
        if (t < off) {
            float* a = vacc + t * VSLOT;
            float* c = vacc + (t + off) * VSLOT;
#pragma unroll
            for (int j = 0; j < 6; j++) a[j] += c[j];
        }
        __syncthreads();
    }
    if (t >= 1 && t <= KK) atomicAdd(&g_var[b][t], vacc[t]);
}

// ---------------------------------------------------------------------------
// Finalize: cooperative smem preload of all scratch, per-b epilogue, output
// write, and scratch reset for the next graph replay.
#define TF 320

__global__ void __launch_bounds__(TF) finalize_kernel(float* __restrict__ out) {
    __shared__ float sh_sums[BB][KK][DD];
    __shared__ float sh_cnt[BB][KK + 1];
    __shared__ float sh_varr[BB][KK + 1];
    __shared__ float s_var[BB], s_dist[BB], s_reg[BB], s_has[BB];
    const int t = threadIdx.x;

    if (t < BB * KK * DD) (&sh_sums[0][0][0])[t] = (&g_sums[0][0][0])[t];
    if (t < BB * (KK + 1)) {
        (&sh_cnt[0][0])[t]  = (float)(&g_cnt[0][0])[t];
        (&sh_varr[0][0])[t] = (&g_var[0][0])[t];
    }
    __syncthreads();

    if (t < BB) {
        const int b = t;
        float cnt[KK], present[KK], N = 0.f;
        float ctr[KK][DD];
#pragma unroll
        for (int k = 0; k < KK; k++) {
            cnt[k] = sh_cnt[b][k + 1];
            present[k] = cnt[k] > 0.f ? 1.f : 0.f;
            N += present[k];
            const float inv = 1.f / fmaxf(cnt[k], 1.f);
#pragma unroll
            for (int d = 0; d < DD; d++) ctr[k][d] = sh_sums[b][k][d] * inv;
        }
        float lv = 0.f;
#pragma unroll
        for (int k = 0; k < KK; k++)
            lv += present[k] * (sh_varr[b][k + 1] / fmaxf(cnt[k], 1.f));
        lv /= fmaxf(N, 1.f);

        float ld = 0.f;
        for (int i = 0; i < KK; i++) {
            for (int j = i + 1; j < KK; j++) {
                if (present[i] > 0.f && present[j] > 0.f) {
                    float dsq = 0.f;
#pragma unroll
                    for (int d = 0; d < DD; d++) {
                        float df = ctr[i][d] - ctr[j][d];
                        dsq = fmaf(df, df, dsq);
                    }
                    float dist = sqrtf(dsq);
                    float term = fmaxf(6.0f - dist, 0.f);  // 2*DELTA_D = 6
                    ld += term * term;
                }
            }
        }
        float npairs = N * (N - 1.f) * 0.5f;
        ld /= (N > 1.f) ? npairs : 1.f;

        float lr = 0.f;
#pragma unroll
        for (int k = 0; k < KK; k++) {
            if (present[k] > 0.f) {
                float nsq = 0.f;
#pragma unroll
                for (int d = 0; d < DD; d++) {
                    float c = ctr[k][d];
                    nsq = fmaf(c, c, nsq);
                }
                lr += sqrtf(nsq);
            }
        }
        lr /= fmaxf(N, 1.f);
        s_var[b] = lv; s_dist[b] = ld; s_reg[b] = lr;
        s_has[b] = (N > 0.f) ? 1.f : 0.f;
    }
    __syncthreads();
    if (t == 0) {
        float hv = 0.f, hd = 0.f, hr = 0.f, hh = 0.f;
#pragma unroll
        for (int b = 0; b < BB; b++) {
            hh += s_has[b];
            hv += s_var[b] * s_has[b];
            hd += s_dist[b] * s_has[b];
            hr += s_reg[b] * s_has[b];
        }
        const float den = fmaxf(hh, 1.f);
        const float var = hv / den, dist = hd / den, reg = hr / den;
        out[0] = var + dist + 0.001f * reg;  // ALPHA=BETA=1, GAMMA=0.001
        out[1] = var;
        out[2] = dist;
        out[3] = reg;
    }

    // reset scratch for the next graph replay
    if (t < BB * KK * DD) (&g_sums[0][0][0])[t] = 0.f;
    if (t < BB * (KK + 1)) {
        (&g_cnt[0][0])[t] = 0;
        (&g_var[0][0])[t] = 0.f;
    }
}

// ---------------------------------------------------------------------------
extern "C" void kernel_launch(void* const* d_in, const int* in_sizes, int n_in,
                              void* d_out, int out_size) {
    const float* emb  = (const float*)d_in[0];
    const int*   mask = (const int*)d_in[1];
    float*       out  = (float*)d_out;

    dim3 g1(GX1, BB);
    pass1_kernel<<<g1, T1>>>(emb, mask);
    dim3 g2(GX2, BB);
    pass2_kernel<<<g2, T2>>>(emb, mask);
    finalize_kernel<<<1, TF>>>(out);
}

// round 15
// speedup vs baseline: 2.8461x; 1.0692x over previous
#include <cuda_runtime.h>
#include <cstdint>

#define BB 8
#define DD 8
#define KK 5
#define PP (512*1024)

// ---- scratch (device globals; zero-initialized at module load; finalize
// resets them at the end of every run so graph replays start clean) ----
__device__ float g_sums[BB][KK][DD];   // per-batch per-instance channel sums
__device__ int   g_cnt[BB][KK + 1];    // per-batch per-slot pixel counts
__device__ float g_var[BB][KK + 1];    // per-batch per-slot variance sums

// ---------------------------------------------------------------------------
// Pass 1: channel-split with REGISTER accumulators (round-14 proven shape).
// Warp w of each block owns channel plane w; all 8 warps sweep the same pixel
// window (mask int4 loads dedupe in L1). Accumulate via the predication-
// friendly ternary-on-accumulator form: ISETP + @p FADD per label.
#define T1 256
#define GX1 512
#define ITER1 8
// coverage: GX1 * 32 lanes * 4 px * ITER1 = 524288 = PP exactly

__global__ void __launch_bounds__(T1) pass1_kernel(const float* __restrict__ emb,
                                                   const int* __restrict__ mask) {
    __shared__ float red[DD][KK];
    const int t = threadIdx.x;
    const int b = blockIdx.y;
    const int w = t >> 5, lane = t & 31;   // w = channel index

    float acc[KK];
#pragma unroll
    for (int k = 0; k < KK; k++) acc[k] = 0.f;

    unsigned long long cnt64 = 0ull;
    const float* ep = emb + (size_t)b * DD * PP + (size_t)w * PP;
    const int*   mb = mask + (size_t)b * PP;
    int p = (blockIdx.x * 32 + lane) * 4;
    const int stride = GX1 * 32 * 4;

#pragma unroll
    for (int it = 0; it < ITER1; it++, p += stride) {
        const int4 lab4 = *reinterpret_cast<const int4*>(mb + p);
        const float4 v  = *reinterpret_cast<const float4*>(ep + p);
        const int labs[4] = {lab4.x, lab4.y, lab4.z, lab4.w};
        const float es[4] = {v.x, v.y, v.z, v.w};
#pragma unroll
        for (int i = 0; i < 4; i++) {
            const int lab = labs[i];
            if (w == 0) cnt64 += 1ull << (lab * 8);   // warp-uniform predicate
#pragma unroll
            for (int k = 0; k < KK; k++)
                acc[k] = (lab == k + 1) ? acc[k] + es[i] : acc[k];
        }
    }

    // per-warp reduction: 5 instance sums for channel w
#pragma unroll
    for (int off = 16; off > 0; off >>= 1) {
#pragma unroll
        for (int k = 0; k < KK; k++)
            acc[k] += __shfl_down_sync(0xffffffffu, acc[k], off);
    }
    if (lane == 0) {
#pragma unroll
        for (int k = 0; k < KK; k++) red[w][k] = acc[k];
    }
    __syncthreads();
    if (t < KK * DD) {
        const int k = t >> 3, d = t & 7;        // g_sums layout [k][d]
        atomicAdd(&g_sums[b][k][d], red[d][k]);
    }

    // counts from warp 0 only (each label count <= 32 fits a byte)
    if (w == 0) {
#pragma unroll
        for (int k = 1; k <= KK; k++) {
            unsigned c = (unsigned)((cnt64 >> (8 * k)) & 0xffull);
            c = __reduce_add_sync(0xffffffffu, c);
            if (lane == 0) atomicAdd(&g_cnt[b][k], (int)c);
        }
    }
}

// ---------------------------------------------------------------------------
// Pass 2: per-pixel hinge-variance term with REGISTER accumulators using the
// proven ternary-on-accumulator predication (no per-pixel smem traffic).
// Centers computed inline in the prologue.
#define T2 256
#define GX2 128

__device__ __forceinline__ float fsqrt_approx(float x) {
    float r;
    asm("sqrt.approx.f32 %0, %1;" : "=f"(r) : "f"(x));
    return r;
}

__global__ void __launch_bounds__(T2) pass2_kernel(const float* __restrict__ emb,
                                                   const int* __restrict__ mask) {
    __shared__ float4 cs4[(KK + 1) * 2];   // centers table, float4-aligned
    __shared__ float red[T2 / 32][KK];
    const int t = threadIdx.x;
    const int b = blockIdx.y;
    const int w = t >> 5, lane = t & 31;

    if (t < (KK + 1) * DD) {
        const int slot = t / DD, d = t % DD;
        float v = 0.f;
        if (slot >= 1)
            v = g_sums[b][slot - 1][d] / fmaxf((float)g_cnt[b][slot], 1.f);
        reinterpret_cast<float*>(cs4)[t] = v;
    }
    __syncthreads();

    float vacc[KK];
#pragma unroll
    for (int k = 0; k < KK; k++) vacc[k] = 0.f;

    const float* eb = emb + (size_t)b * DD * PP;
    const int*   mb = mask + (size_t)b * PP;
    const int stride = GX2 * T2 * 4;

    for (int p0 = (blockIdx.x * T2 + t) * 4; p0 < PP; p0 += stride) {
        const int4 lab4 = *reinterpret_cast<const int4*>(mb + p0);
        float ev[4][DD];
#pragma unroll
        for (int d = 0; d < DD; d++) {
            float4 v = *reinterpret_cast<const float4*>(eb + (size_t)d * PP + p0);
            ev[0][d] = v.x; ev[1][d] = v.y; ev[2][d] = v.z; ev[3][d] = v.w;
        }
        int labs[4] = {lab4.x, lab4.y, lab4.z, lab4.w};
#pragma unroll
        for (int i = 0; i < 4; i++) {
            const int lab = labs[i];
            const float4 clo = cs4[lab * 2];
            const float4 chi = cs4[lab * 2 + 1];
            float d0 = ev[i][0] - clo.x;
            float s  = d0 * d0;
            float d1 = ev[i][1] - clo.y; s = fmaf(d1, d1, s);
            float d2 = ev[i][2] - clo.z; s = fmaf(d2, d2, s);
            float d3 = ev[i][3] - clo.w; s = fmaf(d3, d3, s);
            float d4 = ev[i][4] - chi.x; s = fmaf(d4, d4, s);
            float d5 = ev[i][5] - chi.y; s = fmaf(d5, d5, s);
            float d6 = ev[i][6] - chi.z; s = fmaf(d6, d6, s);
            float d7 = ev[i][7] - chi.w; s = fmaf(d7, d7, s);
            // max(sqrt(s)-0.5,0)^2 == s - sqrt(s) + 0.25 when s > 0.25 else 0
            float val = (s - fsqrt_approx(s)) + 0.25f;
            val = (s > 0.25f) ? val : 0.f;
#pragma unroll
            for (int k = 0; k < KK; k++)
                vacc[k] = (lab == k + 1) ? vacc[k] + val : vacc[k];
        }
    }

    // warp-shuffle reduce the 5 accumulators, then cross-warp via smem
#pragma unroll
    for (int off = 16; off > 0; off >>= 1) {
#pragma unroll
        for (int k = 0; k < KK; k++)
            vacc[k] += __shfl_down_sync(0xffffffffu, vacc[k], off);
    }
    if (lane == 0) {
#pragma unroll
        for (int k = 0; k < KK; k++) red[w][k] = vacc[k];
    }
    __syncthreads();
    if (t < KK) {
        float s = 0.f;
#pragma unroll
        for (int ww = 0; ww < T2 / 32; ww++) s += red[ww][t];
        atomicAdd(&g_var[b][t + 1], s);
    }
}

// ---------------------------------------------------------------------------
// Finalize: cooperative smem preload of all scratch, per-b epilogue, output
// write, and scratch reset for the next graph replay.
#define TF 320

__global__ void __launch_bounds__(TF) finalize_kernel(float* __restrict__ out) {
    __shared__ float sh_sums[BB][KK][DD];
    __shared__ float sh_cnt[BB][KK + 1];
    __shared__ float sh_varr[BB][KK + 1];
    __shared__ float s_var[BB], s_dist[BB], s_reg[BB], s_has[BB];
    const int t = threadIdx.x;

    if (t < BB * KK * DD) (&sh_sums[0][0][0])[t] = (&g_sums[0][0][0])[t];
    if (t < BB * (KK + 1)) {
        (&sh_cnt[0][0])[t]  = (float)(&g_cnt[0][0])[t];
        (&sh_varr[0][0])[t] = (&g_var[0][0])[t];
    }
    __syncthreads();

    if (t < BB) {
        const int b = t;
        float cnt[KK], present[KK], N = 0.f;
        float ctr[KK][DD];
#pragma unroll
        for (int k = 0; k < KK; k++) {
            cnt[k] = sh_cnt[b][k + 1];
            present[k] = cnt[k] > 0.f ? 1.f : 0.f;
            N += present[k];
            const float inv = 1.f / fmaxf(cnt[k], 1.f);
#pragma unroll
            for (int d = 0; d < DD; d++) ctr[k][d] = sh_sums[b][k][d] * inv;
        }
        float lv = 0.f;
#pragma unroll
        for (int k = 0; k < KK; k++)
            lv += present[k] * (sh_varr[b][k + 1] / fmaxf(cnt[k], 1.f));
        lv /= fmaxf(N, 1.f);

        float ld = 0.f;
        for (int i = 0; i < KK; i++) {
            for (int j = i + 1; j < KK; j++) {
                if (present[i] > 0.f && present[j] > 0.f) {
                    float dsq = 0.f;
#pragma unroll
                    for (int d = 0; d < DD; d++) {
                        float df = ctr[i][d] - ctr[j][d];
                        dsq = fmaf(df, df, dsq);
                    }
                    float dist = sqrtf(dsq);
                    float term = fmaxf(6.0f - dist, 0.f);  // 2*DELTA_D = 6
                    ld += term * term;
                }
            }
        }
        float npairs = N * (N - 1.f) * 0.5f;
        ld /= (N > 1.f) ? npairs : 1.f;

        float lr = 0.f;
#pragma unroll
        for (int k = 0; k < KK; k++) {
            if (present[k] > 0.f) {
                float nsq = 0.f;
#pragma unroll
                for (int d = 0; d < DD; d++) {
                    float c = ctr[k][d];
                    nsq = fmaf(c, c, nsq);
                }
                lr += sqrtf(nsq);
            }
        }
        lr /= fmaxf(N, 1.f);
        s_var[b] = lv; s_dist[b] = ld; s_reg[b] = lr;
        s_has[b] = (N > 0.f) ? 1.f : 0.f;
    }
    __syncthreads();
    if (t == 0) {
        float hv = 0.f, hd = 0.f, hr = 0.f, hh = 0.f;
#pragma unroll
        for (int b = 0; b < BB; b++) {
            hh += s_has[b];
            hv += s_var[b] * s_has[b];
            hd += s_dist[b] * s_has[b];
            hr += s_reg[b] * s_has[b];
        }
        const float den = fmaxf(hh, 1.f);
        const float var = hv / den, dist = hd / den, reg = hr / den;
        out[0] = var + dist + 0.001f * reg;  // ALPHA=BETA=1, GAMMA=0.001
        out[1] = var;
        out[2] = dist;
        out[3] = reg;
    }

    // reset scratch for the next graph replay
    if (t < BB * KK * DD) (&g_sums[0][0][0])[t] = 0.f;
    if (t < BB * (KK + 1)) {
        (&g_cnt[0][0])[t] = 0;
        (&g_var[0][0])[t] = 0.f;
    }
}

// ---------------------------------------------------------------------------
extern "C" void kernel_launch(void* const* d_in, const int* in_sizes, int n_in,
                              void* d_out, int out_size) {
    const float* emb  = (const float*)d_in[0];
    const int*   mask = (const int*)d_in[1];
    float*       out  = (float*)d_out;

    dim3 g1(GX1, BB);
    pass1_kernel<<<g1, T1>>>(emb, mask);
    dim3 g2(GX2, BB);
    pass2_kernel<<<g2, T2>>>(emb, mask);
    finalize_kernel<<<1, TF>>>(out);
}